// round 16
// baseline (speedup 1.0000x reference)
#include <cuda_runtime.h>
#include <cuda_bf16.h>
#include <cstdint>

// ---------------- problem constants ----------------
constexpr int Lc = 2048, Ec = 1024, Hc = 16, Dc = 64, Bc = 2;
constexpr int BHc = Bc * Hc;     // 32
constexpr int Mr  = Bc * Lc;     // 4096
constexpr float LOG2E = 1.4426950408889634f;

// ---------------- device scratch ----------------
__device__ __nv_bfloat16 g_xhi[Mr * Ec],  g_xlo[Mr * Ec];
__device__ __nv_bfloat16 g_wthi[3 * Ec * Ec], g_wtlo[3 * Ec * Ec];
__device__ __nv_bfloat16 g_qhi[BHc * Lc * Dc], g_qlo[BHc * Lc * Dc];   // pre-scaled by log2e
__device__ __nv_bfloat16 g_khi[BHc * Lc * Dc], g_klo[BHc * Lc * Dc];
__device__ float         g_v  [BHc * Lc * Dc];
__device__ __nv_bfloat16 g_vthi[BHc * Dc * Lc], g_vtlo[BHc * Dc * Lc];
// E stored TILED: 8lx8m tiles of 128B; tile index ((bh*256+Lt)*256+Mt)
__device__ __nv_bfloat16 g_ehi[(size_t)BHc * Lc * Lc];   // 268MB
__device__ __nv_bfloat16 g_elo[(size_t)BHc * Lc * Lc];   // 268MB
__device__ float         g_psum[(size_t)BHc * 16 * Lc];

// ---------------- helpers ----------------
__device__ __forceinline__ uint32_t smem_u32(const void* p) {
    uint32_t a;
    asm("{ .reg .u64 t; cvta.to.shared.u64 t, %1; cvt.u32.u64 %0, t; }" : "=r"(a) : "l"(p));
    return a;
}
__device__ __forceinline__ void split_bf(float f, __nv_bfloat16& h, __nv_bfloat16& l) {
    h = __float2bfloat16(f);
    l = __float2bfloat16(f - __bfloat162float(h));
}
__device__ __forceinline__ void pack_hilo(float f0, float f1, uint32_t& ph, uint32_t& pl) {
    asm("cvt.rn.bf16x2.f32 %0, %1, %2;" : "=r"(ph) : "f"(f1), "f"(f0));
    float h0 = __uint_as_float(ph << 16);
    float h1 = __uint_as_float(ph & 0xFFFF0000u);
    float r0 = f0 - h0, r1 = f1 - h1;
    asm("cvt.rn.bf16x2.f32 %0, %1, %2;" : "=r"(pl) : "f"(r1), "f"(r0));
}
__device__ __forceinline__ void cp16(uint32_t dst, const void* src) {
    asm volatile("cp.async.cg.shared.global [%0], [%1], 16;" :: "r"(dst), "l"(src));
}
__device__ __forceinline__ void cp_commit() { asm volatile("cp.async.commit_group;"); }
template<int N> __device__ __forceinline__ void cp_wait() {
    asm volatile("cp.async.wait_group %0;" :: "n"(N));
}
#define LDSM4(r, addr) \
    asm volatile("ldmatrix.sync.aligned.m8n8.x4.shared.b16 {%0,%1,%2,%3}, [%4];" \
        : "=r"((r)[0]), "=r"((r)[1]), "=r"((r)[2]), "=r"((r)[3]) : "r"(addr))
#define MMA(d, a, b) \
    asm volatile("mma.sync.aligned.m16n8k16.row.col.f32.bf16.bf16.f32 " \
        "{%0,%1,%2,%3}, {%4,%5,%6,%7}, {%8,%9}, {%0,%1,%2,%3};" \
        : "+f"((d)[0]), "+f"((d)[1]), "+f"((d)[2]), "+f"((d)[3]) \
        : "r"((a)[0]), "r"((a)[1]), "r"((a)[2]), "r"((a)[3]), "r"((b)[0]), "r"((b)[1]))

// ---------------- generic 3-term bf16 GEMM core (2-stage) ----------------
template<int BM, int BN, int WGN, int WM, int BKt>
__device__ __forceinline__ void gemm_core(
    const __nv_bfloat16* __restrict__ Ahi, const __nv_bfloat16* __restrict__ Alo, int lda,
    const __nv_bfloat16* __restrict__ Bhi, const __nv_bfloat16* __restrict__ Blo, int ldb,
    int K, uint32_t sb, float* acc)
{
    constexpr int WNB = BN / WGN;
    constexpr int MT  = WM / 16;
    constexpr int NT  = WNB / 8;
    constexpr int PITCH = BKt * 2 + 16;
    constexpr int CPR = BKt / 8;
    constexpr int ABY = BM * PITCH;
    constexpr int BBY = BN * PITCH;
    constexpr int STG = 2 * ABY + 2 * BBY;

    const int tid = threadIdx.x;
    const int wid = tid >> 5, lane = tid & 31;
    const int wm = wid / WGN, wn = wid % WGN;

    auto issue = [&](int it, int buf) {
        const int k0 = it * BKt;
        const uint32_t base = sb + buf * STG;
        #pragma unroll
        for (int c = tid; c < BM * CPR; c += 256) {
            int row = c / CPR, seg = c % CPR;
            uint32_t d = base + row * PITCH + seg * 16;
            cp16(d,       Ahi + (size_t)row * lda + k0 + seg * 8);
            cp16(d + ABY, Alo + (size_t)row * lda + k0 + seg * 8);
        }
        #pragma unroll
        for (int c = tid; c < BN * CPR; c += 256) {
            int row = c / CPR, seg = c % CPR;
            uint32_t d = base + 2 * ABY + row * PITCH + seg * 16;
            cp16(d,       Bhi + (size_t)row * ldb + k0 + seg * 8);
            cp16(d + BBY, Blo + (size_t)row * ldb + k0 + seg * 8);
        }
        cp_commit();
    };

    auto compute = [&](int buf) {
        const uint32_t aB = sb + buf * STG +
            (uint32_t)((wm * WM + (lane & 15)) * PITCH + ((lane >> 4) << 4));
        const uint32_t bB = sb + buf * STG + 2 * ABY +
            (uint32_t)((wn * WNB + (lane & 7) + (((lane >> 4) & 1) << 3)) * PITCH +
                       (((lane >> 3) & 1) << 4));
        #pragma unroll
        for (int ks = 0; ks < BKt / 16; ks++) {
            uint32_t ah[MT][4], al[MT][4];
            #pragma unroll
            for (int mt = 0; mt < MT; mt++) {
                LDSM4(ah[mt], aB + mt * 16 * PITCH + ks * 32);
                LDSM4(al[mt], aB + ABY + mt * 16 * PITCH + ks * 32);
            }
            uint32_t bh[NT][2], bl[NT][2];
            #pragma unroll
            for (int np = 0; np < NT / 2; np++) {
                uint32_t t[4];
                LDSM4(t, bB + np * 16 * PITCH + ks * 32);
                bh[2*np][0] = t[0]; bh[2*np][1] = t[1];
                bh[2*np+1][0] = t[2]; bh[2*np+1][1] = t[3];
                LDSM4(t, bB + BBY + np * 16 * PITCH + ks * 32);
                bl[2*np][0] = t[0]; bl[2*np][1] = t[1];
                bl[2*np+1][0] = t[2]; bl[2*np+1][1] = t[3];
            }
            #pragma unroll
            for (int mt = 0; mt < MT; mt++)
                #pragma unroll
                for (int nt = 0; nt < NT; nt++) {
                    float* d = acc + (mt * NT + nt) * 4;
                    MMA(d, ah[mt], bh[nt]);
                    MMA(d, ah[mt], bl[nt]);
                    MMA(d, al[mt], bh[nt]);
                }
        }
    };

    const int niter = K / BKt;
    issue(0, 0);
    for (int it = 0; it < niter; it++) {
        if (it + 1 < niter) { issue(it + 1, (it + 1) & 1); cp_wait<1>(); }
        else                { cp_wait<0>(); }
        __syncthreads();
        compute(it & 1);
        __syncthreads();
    }
}

// ---------------- conversion kernels ----------------
__global__ void conv_x(const float* __restrict__ x) {
    int i = blockIdx.x * 256 + threadIdx.x;
    float4 v = reinterpret_cast<const float4*>(x)[i];
    uint32_t h01, l01, h23, l23;
    pack_hilo(v.x, v.y, h01, l01);
    pack_hilo(v.z, v.w, h23, l23);
    reinterpret_cast<uint32_t*>(g_xhi)[i * 2]     = h01;
    reinterpret_cast<uint32_t*>(g_xhi)[i * 2 + 1] = h23;
    reinterpret_cast<uint32_t*>(g_xlo)[i * 2]     = l01;
    reinterpret_cast<uint32_t*>(g_xlo)[i * 2 + 1] = l23;
}

__global__ void conv_w(const float* __restrict__ Wq, const float* __restrict__ Wk,
                       const float* __restrict__ Wv) {
    const float* W = (blockIdx.z == 0) ? Wq : (blockIdx.z == 1) ? Wk : Wv;
    __nv_bfloat16* dh = g_wthi + (size_t)blockIdx.z * Ec * Ec;
    __nv_bfloat16* dl = g_wtlo + (size_t)blockIdx.z * Ec * Ec;
    __shared__ float t[32][33];
    int tx = threadIdx.x, ty = threadIdx.y;
    int k0 = blockIdx.x * 32, n0 = blockIdx.y * 32;
    #pragma unroll
    for (int i = 0; i < 4; i++)
        t[ty + i * 8][tx] = W[(size_t)(k0 + ty + i * 8) * Ec + n0 + tx];
    __syncthreads();
    #pragma unroll
    for (int i = 0; i < 4; i++) {
        float v = t[tx][ty + i * 8];
        __nv_bfloat16 h, l; split_bf(v, h, l);
        size_t o = (size_t)(n0 + ty + i * 8) * Ec + k0 + tx;
        dh[o] = h; dl[o] = l;
    }
}

// ---------------- GEMM 1: QKV projection (128x64 tile, BK=64) ----------------
__global__ void __launch_bounds__(256) k_proj_t(const float* __restrict__ bq,
                                                const float* __restrict__ bk,
                                                const float* __restrict__ bv,
                                                int zbase) {
    extern __shared__ char smem[];
    uint32_t sb = smem_u32(smem);
    const int tid = threadIdx.x;
    const int z = blockIdx.z + zbase;
    const int n0 = blockIdx.x * 64, m0 = blockIdx.y * 128;
    const float* bias = (z == 0) ? bq : (z == 1) ? bk : bv;
    const __nv_bfloat16* Whi = g_wthi + (size_t)z * Ec * Ec;
    const __nv_bfloat16* Wlo = g_wtlo + (size_t)z * Ec * Ec;
    const float scl = (z == 0) ? LOG2E : 1.0f;

    float acc[32] = {};
    gemm_core<128, 64, 2, 32, 64>(g_xhi + (size_t)m0 * Ec, g_xlo + (size_t)m0 * Ec, Ec,
                                  Whi + (size_t)n0 * Ec,   Wlo + (size_t)n0 * Ec,   Ec,
                                  Ec, sb, acc);

    float* stage = reinterpret_cast<float*>(smem);   // 128 x pitch68
    const int wid = tid >> 5, lane = tid & 31;
    const int wm = wid >> 1, wn = wid & 1;
    #pragma unroll
    for (int mt = 0; mt < 2; mt++)
        #pragma unroll
        for (int nt = 0; nt < 4; nt++) {
            int r0 = wm * 32 + mt * 16 + (lane >> 2);
            int c0 = wn * 32 + nt * 8 + (lane & 3) * 2;
            float* d = acc + (mt * 4 + nt) * 4;
            stage[r0 * 68 + c0] = d[0]; stage[r0 * 68 + c0 + 1] = d[1];
            stage[(r0 + 8) * 68 + c0] = d[2]; stage[(r0 + 8) * 68 + c0 + 1] = d[3];
        }
    __syncthreads();

    const int h = n0 >> 6;   // single head per block
    if (z < 2) {
        __nv_bfloat16* dh = (z == 0) ? g_qhi : g_khi;
        __nv_bfloat16* dl = (z == 0) ? g_qlo : g_klo;
        for (int c = tid; c < 1024; c += 256) {      // 128 rows x 8 chunks(16B)
            int row = c >> 3, seg = c & 7;
            int m = m0 + row, b = m >> 11, l = m & 2047;
            uint32_t ph[4], pl[4];
            #pragma unroll
            for (int j = 0; j < 4; j++) {
                float f0 = (stage[row * 68 + seg * 8 + 2 * j] +
                            bias[n0 + seg * 8 + 2 * j]) * scl;
                float f1 = (stage[row * 68 + seg * 8 + 2 * j + 1] +
                            bias[n0 + seg * 8 + 2 * j + 1]) * scl;
                pack_hilo(f0, f1, ph[j], pl[j]);
            }
            size_t o = ((size_t)(b * Hc + h) * Lc + l) * Dc + seg * 8;
            *reinterpret_cast<uint4*>(dh + o) = make_uint4(ph[0], ph[1], ph[2], ph[3]);
            *reinterpret_cast<uint4*>(dl + o) = make_uint4(pl[0], pl[1], pl[2], pl[3]);
        }
    } else {
        for (int c = tid; c < 2048; c += 256) {      // 128 rows x 16 float4
            int row = c >> 4, seg = c & 15;
            int m = m0 + row, b = m >> 11, l = m & 2047;
            float4 v;
            v.x = stage[row * 68 + seg * 4 + 0] + bias[n0 + seg * 4 + 0];
            v.y = stage[row * 68 + seg * 4 + 1] + bias[n0 + seg * 4 + 1];
            v.z = stage[row * 68 + seg * 4 + 2] + bias[n0 + seg * 4 + 2];
            v.w = stage[row * 68 + seg * 4 + 3] + bias[n0 + seg * 4 + 3];
            *reinterpret_cast<float4*>(g_v + ((size_t)(b * Hc + h) * Lc + l) * Dc + seg * 4) = v;
        }
    }
}

// ---------------- GEMM 2: scores + exp2 + colsums; E stored TILED from regs ----------------
__global__ void __launch_bounds__(256) k_scores_t() {
    extern __shared__ char smem[];
    uint32_t sb = smem_u32(smem);
    const int tid = threadIdx.x;
    const int bh = blockIdx.z, m0 = blockIdx.x * 128, l0 = blockIdx.y * 128;

    float acc[64] = {};
    gemm_core<128, 128, 4, 64, 32>(g_qhi + ((size_t)bh * Lc + l0) * Dc,
                                   g_qlo + ((size_t)bh * Lc + l0) * Dc, Dc,
                                   g_khi + ((size_t)bh * Lc + m0) * Dc,
                                   g_klo + ((size_t)bh * Lc + m0) * Dc, Dc,
                                   Dc, sb, acc);

    float* colp = reinterpret_cast<float*>(smem);      // [2][128]
    const int wid = tid >> 5, lane = tid & 31;
    const int wm = wid >> 2, wn = wid & 3;

    // tile base for this block: tiles are 8l x 8m = 128B
    const size_t tb = ((size_t)bh * 256 + (l0 >> 3)) * 256 + (m0 >> 3);
    char* ehiB = reinterpret_cast<char*>(g_ehi);
    char* eloB = reinterpret_cast<char*>(g_elo);

    float cs[4][2] = {};
    #pragma unroll
    for (int mt = 0; mt < 4; mt++)
        #pragma unroll
        for (int nt = 0; nt < 4; nt++) {
            float* d = acc + (mt * 4 + nt) * 4;
            float e0 = exp2f(d[0]), e1 = exp2f(d[1]);
            float e2 = exp2f(d[2]), e3 = exp2f(d[3]);
            cs[nt][0] += e0 + e2;
            cs[nt][1] += e1 + e3;
            uint32_t ph0, pl0, ph1, pl1;
            pack_hilo(e0, e1, ph0, pl0);
            pack_hilo(e2, e3, ph1, pl1);
            // l-tile (relative): rows r0 block = wm*8 + mt*2, second +1; m-tile: wn*4+nt
            size_t t0 = tb + (size_t)(wm * 8 + mt * 2) * 256 + (wn * 4 + nt);
            size_t o0 = (t0 << 7) + lane * 4;
            *reinterpret_cast<uint32_t*>(ehiB + o0) = ph0;
            *reinterpret_cast<uint32_t*>(eloB + o0) = pl0;
            size_t o1 = o0 + (256u << 7);   // next l-tile
            *reinterpret_cast<uint32_t*>(ehiB + o1) = ph1;
            *reinterpret_cast<uint32_t*>(eloB + o1) = pl1;
        }

    #pragma unroll
    for (int nt = 0; nt < 4; nt++)
        #pragma unroll
        for (int p = 0; p < 2; p++) {
            float v = cs[nt][p];
            v += __shfl_xor_sync(0xffffffffu, v, 4);
            v += __shfl_xor_sync(0xffffffffu, v, 8);
            v += __shfl_xor_sync(0xffffffffu, v, 16);
            cs[nt][p] = v;
        }
    __syncthreads();   // colp region reuses mainloop smem
    if (lane < 4) {
        #pragma unroll
        for (int nt = 0; nt < 4; nt++) {
            int cp = wn * 16 + nt * 4 + lane;
            colp[wm * 128 + cp * 2]     = cs[nt][0];
            colp[wm * 128 + cp * 2 + 1] = cs[nt][1];
        }
    }
    __syncthreads();
    if (tid < 128)
        g_psum[((size_t)bh * 16 + blockIdx.y) * Lc + m0 + tid] = colp[tid] + colp[128 + tid];
}

// ---------------- Vs^T = (V * dinv)^T as bf16 hi/lo (dinv fused) ----------------
__global__ void k_vscale() {
    __shared__ float tv[64][65];
    __shared__ float dsm[64];
    int tid = threadIdx.x;
    int bh = blockIdx.y, m0 = blockIdx.x * 64;
    if (tid < 64) {
        float s = 0.0f;
        #pragma unroll
        for (int j = 0; j < 16; j++) s += g_psum[((size_t)bh * 16 + j) * Lc + m0 + tid];
        dsm[tid] = 1.0f / s;
    }
    __syncthreads();
    const float* V = g_v + ((size_t)bh * Lc + m0) * Dc;
    #pragma unroll
    for (int i = 0; i < 16; i++) {
        int e = tid + i * 256;
        int r = e >> 6, d = e & 63;
        tv[r][d] = V[r * Dc + d] * dsm[r];
    }
    __syncthreads();
    #pragma unroll
    for (int i = 0; i < 16; i++) {
        int e = tid + i * 256;
        int d = e >> 6, c = e & 63;
        float v = tv[c][d];
        __nv_bfloat16 h, l; split_bf(v, h, l);
        size_t o = ((size_t)bh * Dc + d) * Lc + m0 + c;
        g_vthi[o] = h; g_vtlo[o] = l;
    }
}

// ---------------- GEMM 3: out = E(tiled) * Vs^T (128x64, BK=64) ----------------
__global__ void __launch_bounds__(256) k_pv_t(float* __restrict__ outF) {
    extern __shared__ char smem[];
    uint32_t sb = smem_u32(smem);
    const int tid = threadIdx.x;
    const int wid = tid >> 5, lane = tid & 31;
    const int bh = blockIdx.y, b = bh >> 4, h = bh & 15;
    const int l0 = blockIdx.x * 128;

    constexpr int PITCH = 144;                  // BK=64
    constexpr int ABY = 128 * PITCH;            // 18432
    constexpr int BBY = 64 * PITCH;             // 9216
    constexpr int STG = 2 * ABY + 2 * BBY;      // 55296

    const char* ehiB = reinterpret_cast<const char*>(g_ehi);
    const char* eloB = reinterpret_cast<const char*>(g_elo);
    const size_t ltb = ((size_t)bh * 256 + (l0 >> 3)) * 256;   // tile row base for this block
    const __nv_bfloat16* Bhi = g_vthi + (size_t)bh * Dc * Lc;
    const __nv_bfloat16* Blo = g_vtlo + (size_t)bh * Dc * Lc;

    auto issue = [&](int it, int buf) {
        const int k0 = it * 64;
        const uint32_t base = sb + buf * STG;
        #pragma unroll
        for (int c = tid; c < 1024; c += 256) {     // 128 rows x 8 segs
            int row = c >> 3, seg = c & 7;
            uint32_t d = base + row * PITCH + seg * 16;
            size_t off = ((ltb + (size_t)(row >> 3) * 256 + (k0 >> 3) + seg) << 7)
                         + ((row & 7) << 4);
            cp16(d,       ehiB + off);
            cp16(d + ABY, eloB + off);
        }
        #pragma unroll
        for (int c = tid; c < 512; c += 256) {      // 64 rows x 8 segs
            int row = c >> 3, seg = c & 7;
            uint32_t d = base + 2 * ABY + row * PITCH + seg * 16;
            cp16(d,       Bhi + (size_t)row * Lc + k0 + seg * 8);
            cp16(d + BBY, Blo + (size_t)row * Lc + k0 + seg * 8);
        }
        cp_commit();
    };

    const int wm = wid >> 1, wn = wid & 1;
    float acc[32] = {};

    auto compute = [&](int buf) {
        const uint32_t aB = sb + buf * STG +
            (uint32_t)((wm * 32 + (lane & 15)) * PITCH + ((lane >> 4) << 4));
        const uint32_t bB = sb + buf * STG + 2 * ABY +
            (uint32_t)((wn * 32 + (lane & 7) + (((lane >> 4) & 1) << 3)) * PITCH +
                       (((lane >> 3) & 1) << 4));
        #pragma unroll
        for (int ks = 0; ks < 4; ks++) {
            uint32_t ah[2][4], al[2][4];
            #pragma unroll
            for (int mt = 0; mt < 2; mt++) {
                LDSM4(ah[mt], aB + mt * 16 * PITCH + ks * 32);
                LDSM4(al[mt], aB + ABY + mt * 16 * PITCH + ks * 32);
            }
            uint32_t bhf[4][2], blf[4][2];
            #pragma unroll
            for (int np = 0; np < 2; np++) {
                uint32_t t[4];
                LDSM4(t, bB + np * 16 * PITCH + ks * 32);
                bhf[2*np][0] = t[0]; bhf[2*np][1] = t[1];
                bhf[2*np+1][0] = t[2]; bhf[2*np+1][1] = t[3];
                LDSM4(t, bB + BBY + np * 16 * PITCH + ks * 32);
                blf[2*np][0] = t[0]; blf[2*np][1] = t[1];
                blf[2*np+1][0] = t[2]; blf[2*np+1][1] = t[3];
            }
            #pragma unroll
            for (int mt = 0; mt < 2; mt++)
                #pragma unroll
                for (int nt = 0; nt < 4; nt++) {
                    float* d = acc + (mt * 4 + nt) * 4;
                    MMA(d, ah[mt], bhf[nt]);
                    MMA(d, ah[mt], blf[nt]);
                    MMA(d, al[mt], bhf[nt]);
                }
        }
    };

    issue(0, 0);
    for (int it = 0; it < 32; it++) {
        if (it + 1 < 32) { issue(it + 1, (it + 1) & 1); cp_wait<1>(); }
        else             { cp_wait<0>(); }
        __syncthreads();
        compute(it & 1);
        __syncthreads();
    }

    float* stage = reinterpret_cast<float*>(smem);     // 128 x pitch68
    #pragma unroll
    for (int mt = 0; mt < 2; mt++)
        #pragma unroll
        for (int nt = 0; nt < 4; nt++) {
            int r0 = wm * 32 + mt * 16 + (lane >> 2);
            int c0 = wn * 32 + nt * 8 + (lane & 3) * 2;
            float* d = acc + (mt * 4 + nt) * 4;
            stage[r0 * 68 + c0] = d[0]; stage[r0 * 68 + c0 + 1] = d[1];
            stage[(r0 + 8) * 68 + c0] = d[2]; stage[(r0 + 8) * 68 + c0 + 1] = d[3];
        }
    __syncthreads();
    for (int c = tid; c < 2048; c += 256) {
        int row = c >> 4, seg = c & 15;
        float4 v = *reinterpret_cast<float4*>(&stage[row * 68 + seg * 4]);
        *reinterpret_cast<float4*>(outF + ((size_t)b * Lc + l0 + row) * Ec + h * Dc + seg * 4) = v;
    }
}

// ---------------- launch (fork-join overlap: projV || scores) ----------------
extern "C" void kernel_launch(void* const* d_in, const int* in_sizes, int n_in,
                              void* d_out, int out_size) {
    const float* x  = (const float*)d_in[0];
    const float* Wq = (const float*)d_in[1];
    const float* bq = (const float*)d_in[2];
    const float* Wk = (const float*)d_in[3];
    const float* bk = (const float*)d_in[4];
    const float* Wv = (const float*)d_in[5];
    const float* bv = (const float*)d_in[6];
    float* out = (float*)d_out;

    static bool init_done = false;
    static cudaStream_t s1;
    static cudaEvent_t ev0, evX, evW, evV;
    if (!init_done) {
        cudaStreamCreateWithFlags(&s1, cudaStreamNonBlocking);
        cudaEventCreateWithFlags(&ev0, cudaEventDisableTiming);
        cudaEventCreateWithFlags(&evX, cudaEventDisableTiming);
        cudaEventCreateWithFlags(&evW, cudaEventDisableTiming);
        cudaEventCreateWithFlags(&evV, cudaEventDisableTiming);
        cudaFuncSetAttribute(k_proj_t,   cudaFuncAttributeMaxDynamicSharedMemorySize, 110592);
        cudaFuncSetAttribute(k_scores_t, cudaFuncAttributeMaxDynamicSharedMemorySize, 81920);
        cudaFuncSetAttribute(k_pv_t,     cudaFuncAttributeMaxDynamicSharedMemorySize, 110592);
        init_done = true;
    }

    cudaEventRecord(ev0, 0);
    cudaStreamWaitEvent(s1, ev0, 0);
    conv_x<<<Mr * Ec / 1024, 256, 0, s1>>>(x);
    cudaEventRecord(evX, s1);

    conv_w<<<dim3(32, 32, 3), dim3(32, 8)>>>(Wq, Wk, Wv);
    cudaEventRecord(evW, 0);

    cudaStreamWaitEvent(0, evX, 0);
    k_proj_t<<<dim3(16, 32, 2), 256, 110592>>>(bq, bk, bv, 0);

    cudaStreamWaitEvent(s1, evW, 0);
    k_proj_t<<<dim3(16, 32, 1), 256, 110592, s1>>>(bq, bk, bv, 2);
    cudaEventRecord(evV, s1);

    k_scores_t<<<dim3(16, 16, 32), 256, 81920>>>();

    cudaStreamWaitEvent(0, evV, 0);
    k_vscale<<<dim3(32, 32), 256>>>();
    k_pv_t<<<dim3(16, 32), 256, 110592>>>(out);
}

// round 17
// speedup vs baseline: 1.2035x; 1.2035x over previous
#include <cuda_runtime.h>
#include <cuda_bf16.h>
#include <cstdint>

// ---------------- problem constants ----------------
constexpr int Lc = 2048, Ec = 1024, Hc = 16, Dc = 64, Bc = 2;
constexpr int BHc = Bc * Hc;     // 32
constexpr int Mr  = Bc * Lc;     // 4096
constexpr float LOG2E = 1.4426950408889634f;

// ---------------- device scratch ----------------
__device__ __nv_bfloat16 g_xhi[Mr * Ec],  g_xlo[Mr * Ec];
__device__ __nv_bfloat16 g_wthi[3 * Ec * Ec], g_wtlo[3 * Ec * Ec];
__device__ __nv_bfloat16 g_qhi[BHc * Lc * Dc], g_qlo[BHc * Lc * Dc];   // pre-scaled by log2e
__device__ __nv_bfloat16 g_khi[BHc * Lc * Dc], g_klo[BHc * Lc * Dc];
__device__ float         g_v  [BHc * Lc * Dc];
__device__ __nv_bfloat16 g_vthi[BHc * Dc * Lc], g_vtlo[BHc * Dc * Lc];
__device__ __nv_bfloat16 g_ehi[(size_t)BHc * Lc * Lc];   // 268MB
__device__ __nv_bfloat16 g_elo[(size_t)BHc * Lc * Lc];   // 268MB
__device__ float         g_psum[(size_t)BHc * 16 * Lc];

// ---------------- helpers ----------------
__device__ __forceinline__ uint32_t smem_u32(const void* p) {
    uint32_t a;
    asm("{ .reg .u64 t; cvta.to.shared.u64 t, %1; cvt.u32.u64 %0, t; }" : "=r"(a) : "l"(p));
    return a;
}
__device__ __forceinline__ void split_bf(float f, __nv_bfloat16& h, __nv_bfloat16& l) {
    h = __float2bfloat16(f);
    l = __float2bfloat16(f - __bfloat162float(h));
}
__device__ __forceinline__ void pack_hilo(float f0, float f1, uint32_t& ph, uint32_t& pl) {
    asm("cvt.rn.bf16x2.f32 %0, %1, %2;" : "=r"(ph) : "f"(f1), "f"(f0));
    float h0 = __uint_as_float(ph << 16);
    float h1 = __uint_as_float(ph & 0xFFFF0000u);
    float r0 = f0 - h0, r1 = f1 - h1;
    asm("cvt.rn.bf16x2.f32 %0, %1, %2;" : "=r"(pl) : "f"(r1), "f"(r0));
}
__device__ __forceinline__ void cp16(uint32_t dst, const void* src) {
    asm volatile("cp.async.cg.shared.global [%0], [%1], 16;" :: "r"(dst), "l"(src));
}
__device__ __forceinline__ void cp_commit() { asm volatile("cp.async.commit_group;"); }
template<int N> __device__ __forceinline__ void cp_wait() {
    asm volatile("cp.async.wait_group %0;" :: "n"(N));
}
#define LDSM4(r, addr) \
    asm volatile("ldmatrix.sync.aligned.m8n8.x4.shared.b16 {%0,%1,%2,%3}, [%4];" \
        : "=r"((r)[0]), "=r"((r)[1]), "=r"((r)[2]), "=r"((r)[3]) : "r"(addr))
#define MMA(d, a, b) \
    asm volatile("mma.sync.aligned.m16n8k16.row.col.f32.bf16.bf16.f32 " \
        "{%0,%1,%2,%3}, {%4,%5,%6,%7}, {%8,%9}, {%0,%1,%2,%3};" \
        : "+f"((d)[0]), "+f"((d)[1]), "+f"((d)[2]), "+f"((d)[3]) \
        : "r"((a)[0]), "r"((a)[1]), "r"((a)[2]), "r"((a)[3]), "r"((b)[0]), "r"((b)[1]))

// ---------------- generic 3-term bf16 GEMM core (2-stage) ----------------
template<int BM, int BN, int WGN, int WM, int BKt>
__device__ __forceinline__ void gemm_core(
    const __nv_bfloat16* __restrict__ Ahi, const __nv_bfloat16* __restrict__ Alo, int lda,
    const __nv_bfloat16* __restrict__ Bhi, const __nv_bfloat16* __restrict__ Blo, int ldb,
    int K, uint32_t sb, float* acc)
{
    constexpr int WNB = BN / WGN;
    constexpr int MT  = WM / 16;
    constexpr int NT  = WNB / 8;
    constexpr int PITCH = BKt * 2 + 16;
    constexpr int CPR = BKt / 8;
    constexpr int ABY = BM * PITCH;
    constexpr int BBY = BN * PITCH;
    constexpr int STG = 2 * ABY + 2 * BBY;

    const int tid = threadIdx.x;
    const int wid = tid >> 5, lane = tid & 31;
    const int wm = wid / WGN, wn = wid % WGN;

    auto issue = [&](int it, int buf) {
        const int k0 = it * BKt;
        const uint32_t base = sb + buf * STG;
        #pragma unroll
        for (int c = tid; c < BM * CPR; c += 256) {
            int row = c / CPR, seg = c % CPR;
            uint32_t d = base + row * PITCH + seg * 16;
            cp16(d,       Ahi + (size_t)row * lda + k0 + seg * 8);
            cp16(d + ABY, Alo + (size_t)row * lda + k0 + seg * 8);
        }
        #pragma unroll
        for (int c = tid; c < BN * CPR; c += 256) {
            int row = c / CPR, seg = c % CPR;
            uint32_t d = base + 2 * ABY + row * PITCH + seg * 16;
            cp16(d,       Bhi + (size_t)row * ldb + k0 + seg * 8);
            cp16(d + BBY, Blo + (size_t)row * ldb + k0 + seg * 8);
        }
        cp_commit();
    };

    auto compute = [&](int buf) {
        const uint32_t aB = sb + buf * STG +
            (uint32_t)((wm * WM + (lane & 15)) * PITCH + ((lane >> 4) << 4));
        const uint32_t bB = sb + buf * STG + 2 * ABY +
            (uint32_t)((wn * WNB + (lane & 7) + (((lane >> 4) & 1) << 3)) * PITCH +
                       (((lane >> 3) & 1) << 4));
        #pragma unroll
        for (int ks = 0; ks < BKt / 16; ks++) {
            uint32_t ah[MT][4], al[MT][4];
            #pragma unroll
            for (int mt = 0; mt < MT; mt++) {
                LDSM4(ah[mt], aB + mt * 16 * PITCH + ks * 32);
                LDSM4(al[mt], aB + ABY + mt * 16 * PITCH + ks * 32);
            }
            uint32_t bh[NT][2], bl[NT][2];
            #pragma unroll
            for (int np = 0; np < NT / 2; np++) {
                uint32_t t[4];
                LDSM4(t, bB + np * 16 * PITCH + ks * 32);
                bh[2*np][0] = t[0]; bh[2*np][1] = t[1];
                bh[2*np+1][0] = t[2]; bh[2*np+1][1] = t[3];
                LDSM4(t, bB + BBY + np * 16 * PITCH + ks * 32);
                bl[2*np][0] = t[0]; bl[2*np][1] = t[1];
                bl[2*np+1][0] = t[2]; bl[2*np+1][1] = t[3];
            }
            #pragma unroll
            for (int mt = 0; mt < MT; mt++)
                #pragma unroll
                for (int nt = 0; nt < NT; nt++) {
                    float* d = acc + (mt * NT + nt) * 4;
                    MMA(d, ah[mt], bh[nt]);
                    MMA(d, ah[mt], bl[nt]);
                    MMA(d, al[mt], bh[nt]);
                }
        }
    };

    const int niter = K / BKt;
    issue(0, 0);
    for (int it = 0; it < niter; it++) {
        if (it + 1 < niter) { issue(it + 1, (it + 1) & 1); cp_wait<1>(); }
        else                { cp_wait<0>(); }
        __syncthreads();
        compute(it & 1);
        __syncthreads();
    }
}

// ---------------- conversion kernels ----------------
__global__ void conv_x(const float* __restrict__ x) {
    int i = blockIdx.x * 256 + threadIdx.x;
    float4 v = reinterpret_cast<const float4*>(x)[i];
    uint32_t h01, l01, h23, l23;
    pack_hilo(v.x, v.y, h01, l01);
    pack_hilo(v.z, v.w, h23, l23);
    reinterpret_cast<uint32_t*>(g_xhi)[i * 2]     = h01;
    reinterpret_cast<uint32_t*>(g_xhi)[i * 2 + 1] = h23;
    reinterpret_cast<uint32_t*>(g_xlo)[i * 2]     = l01;
    reinterpret_cast<uint32_t*>(g_xlo)[i * 2 + 1] = l23;
}

__global__ void conv_w(const float* __restrict__ Wq, const float* __restrict__ Wk,
                       const float* __restrict__ Wv) {
    const float* W = (blockIdx.z == 0) ? Wq : (blockIdx.z == 1) ? Wk : Wv;
    __nv_bfloat16* dh = g_wthi + (size_t)blockIdx.z * Ec * Ec;
    __nv_bfloat16* dl = g_wtlo + (size_t)blockIdx.z * Ec * Ec;
    __shared__ float t[32][33];
    int tx = threadIdx.x, ty = threadIdx.y;
    int k0 = blockIdx.x * 32, n0 = blockIdx.y * 32;
    #pragma unroll
    for (int i = 0; i < 4; i++)
        t[ty + i * 8][tx] = W[(size_t)(k0 + ty + i * 8) * Ec + n0 + tx];
    __syncthreads();
    #pragma unroll
    for (int i = 0; i < 4; i++) {
        float v = t[tx][ty + i * 8];
        __nv_bfloat16 h, l; split_bf(v, h, l);
        size_t o = (size_t)(n0 + ty + i * 8) * Ec + k0 + tx;
        dh[o] = h; dl[o] = l;
    }
}

// ---------------- GEMM 1: QKV projection (128x64 tile, BK=64) ----------------
__global__ void __launch_bounds__(256) k_proj_t(const float* __restrict__ bq,
                                                const float* __restrict__ bk,
                                                const float* __restrict__ bv,
                                                int zbase) {
    extern __shared__ char smem[];
    uint32_t sb = smem_u32(smem);
    const int tid = threadIdx.x;
    const int z = blockIdx.z + zbase;
    const int n0 = blockIdx.x * 64, m0 = blockIdx.y * 128;
    const float* bias = (z == 0) ? bq : (z == 1) ? bk : bv;
    const __nv_bfloat16* Whi = g_wthi + (size_t)z * Ec * Ec;
    const __nv_bfloat16* Wlo = g_wtlo + (size_t)z * Ec * Ec;
    const float scl = (z == 0) ? LOG2E : 1.0f;

    float acc[32] = {};
    gemm_core<128, 64, 2, 32, 64>(g_xhi + (size_t)m0 * Ec, g_xlo + (size_t)m0 * Ec, Ec,
                                  Whi + (size_t)n0 * Ec,   Wlo + (size_t)n0 * Ec,   Ec,
                                  Ec, sb, acc);

    float* stage = reinterpret_cast<float*>(smem);   // 128 x pitch68
    const int wid = tid >> 5, lane = tid & 31;
    const int wm = wid >> 1, wn = wid & 1;
    #pragma unroll
    for (int mt = 0; mt < 2; mt++)
        #pragma unroll
        for (int nt = 0; nt < 4; nt++) {
            int r0 = wm * 32 + mt * 16 + (lane >> 2);
            int c0 = wn * 32 + nt * 8 + (lane & 3) * 2;
            float* d = acc + (mt * 4 + nt) * 4;
            stage[r0 * 68 + c0] = d[0]; stage[r0 * 68 + c0 + 1] = d[1];
            stage[(r0 + 8) * 68 + c0] = d[2]; stage[(r0 + 8) * 68 + c0 + 1] = d[3];
        }
    __syncthreads();

    const int h = n0 >> 6;   // single head per block
    if (z < 2) {
        __nv_bfloat16* dh = (z == 0) ? g_qhi : g_khi;
        __nv_bfloat16* dl = (z == 0) ? g_qlo : g_klo;
        for (int c = tid; c < 1024; c += 256) {      // 128 rows x 8 chunks(16B)
            int row = c >> 3, seg = c & 7;
            int m = m0 + row, b = m >> 11, l = m & 2047;
            uint32_t ph[4], pl[4];
            #pragma unroll
            for (int j = 0; j < 4; j++) {
                float f0 = (stage[row * 68 + seg * 8 + 2 * j] +
                            bias[n0 + seg * 8 + 2 * j]) * scl;
                float f1 = (stage[row * 68 + seg * 8 + 2 * j + 1] +
                            bias[n0 + seg * 8 + 2 * j + 1]) * scl;
                pack_hilo(f0, f1, ph[j], pl[j]);
            }
            size_t o = ((size_t)(b * Hc + h) * Lc + l) * Dc + seg * 8;
            *reinterpret_cast<uint4*>(dh + o) = make_uint4(ph[0], ph[1], ph[2], ph[3]);
            *reinterpret_cast<uint4*>(dl + o) = make_uint4(pl[0], pl[1], pl[2], pl[3]);
        }
    } else {
        for (int c = tid; c < 2048; c += 256) {      // 128 rows x 16 float4
            int row = c >> 4, seg = c & 15;
            int m = m0 + row, b = m >> 11, l = m & 2047;
            float4 v;
            v.x = stage[row * 68 + seg * 4 + 0] + bias[n0 + seg * 4 + 0];
            v.y = stage[row * 68 + seg * 4 + 1] + bias[n0 + seg * 4 + 1];
            v.z = stage[row * 68 + seg * 4 + 2] + bias[n0 + seg * 4 + 2];
            v.w = stage[row * 68 + seg * 4 + 3] + bias[n0 + seg * 4 + 3];
            *reinterpret_cast<float4*>(g_v + ((size_t)(b * Hc + h) * Lc + l) * Dc + seg * 4) = v;
        }
    }
}

// ---------------- GEMM 2: scores + exp2 + column partial sums ----------------
__global__ void __launch_bounds__(256) k_scores_t() {
    extern __shared__ char smem[];
    uint32_t sb = smem_u32(smem);
    const int tid = threadIdx.x;
    const int bh = blockIdx.z, m0 = blockIdx.x * 128, l0 = blockIdx.y * 128;

    float acc[64] = {};
    gemm_core<128, 128, 4, 64, 32>(g_qhi + ((size_t)bh * Lc + l0) * Dc,
                                   g_qlo + ((size_t)bh * Lc + l0) * Dc, Dc,
                                   g_khi + ((size_t)bh * Lc + m0) * Dc,
                                   g_klo + ((size_t)bh * Lc + m0) * Dc, Dc,
                                   Dc, sb, acc);

    uint32_t* stH = reinterpret_cast<uint32_t*>(smem);            // [128][68]
    uint32_t* stL = stH + 128 * 68;
    float* colp = reinterpret_cast<float*>(stL + 128 * 68);       // [2][128]
    const int wid = tid >> 5, lane = tid & 31;
    const int wm = wid >> 2, wn = wid & 3;

    float cs[4][2] = {};
    #pragma unroll
    for (int mt = 0; mt < 4; mt++)
        #pragma unroll
        for (int nt = 0; nt < 4; nt++) {
            float* d = acc + (mt * 4 + nt) * 4;
            int r0 = wm * 64 + mt * 16 + (lane >> 2);
            int cp = wn * 16 + nt * 4 + (lane & 3);
            float e0 = exp2f(d[0]), e1 = exp2f(d[1]);
            float e2 = exp2f(d[2]), e3 = exp2f(d[3]);
            cs[nt][0] += e0 + e2;
            cs[nt][1] += e1 + e3;
            uint32_t ph, pl;
            pack_hilo(e0, e1, ph, pl);
            stH[r0 * 68 + cp] = ph; stL[r0 * 68 + cp] = pl;
            pack_hilo(e2, e3, ph, pl);
            stH[(r0 + 8) * 68 + cp] = ph; stL[(r0 + 8) * 68 + cp] = pl;
        }

    #pragma unroll
    for (int nt = 0; nt < 4; nt++)
        #pragma unroll
        for (int p = 0; p < 2; p++) {
            float v = cs[nt][p];
            v += __shfl_xor_sync(0xffffffffu, v, 4);
            v += __shfl_xor_sync(0xffffffffu, v, 8);
            v += __shfl_xor_sync(0xffffffffu, v, 16);
            cs[nt][p] = v;
        }
    if (lane < 4) {
        #pragma unroll
        for (int nt = 0; nt < 4; nt++) {
            int cp = wn * 16 + nt * 4 + lane;
            colp[wm * 128 + cp * 2]     = cs[nt][0];
            colp[wm * 128 + cp * 2 + 1] = cs[nt][1];
        }
    }
    __syncthreads();
    if (tid < 128)
        g_psum[((size_t)bh * 16 + blockIdx.y) * Lc + m0 + tid] = colp[tid] + colp[128 + tid];

    // E writes: coalesced 16B, streaming hint (written once, read once)
    for (int c = tid; c < 2048; c += 256) {      // 128 rows x 16 uint4
        int row = c >> 4, seg = c & 15;
        size_t o = ((size_t)bh * Lc + l0 + row) * Lc + m0 + seg * 8;
        __stcs(reinterpret_cast<uint4*>(g_ehi + o),
               *reinterpret_cast<uint4*>(&stH[row * 68 + seg * 4]));
        __stcs(reinterpret_cast<uint4*>(g_elo + o),
               *reinterpret_cast<uint4*>(&stL[row * 68 + seg * 4]));
    }
}

// ---------------- Vs^T = (V * dinv)^T as bf16 hi/lo (dinv fused) ----------------
__global__ void k_vscale() {
    __shared__ float tv[64][65];
    __shared__ float dsm[64];
    int tid = threadIdx.x;
    int bh = blockIdx.y, m0 = blockIdx.x * 64;
    if (tid < 64) {
        float s = 0.0f;
        #pragma unroll
        for (int j = 0; j < 16; j++) s += g_psum[((size_t)bh * 16 + j) * Lc + m0 + tid];
        dsm[tid] = 1.0f / s;
    }
    __syncthreads();
    const float* V = g_v + ((size_t)bh * Lc + m0) * Dc;
    #pragma unroll
    for (int i = 0; i < 16; i++) {
        int e = tid + i * 256;
        int r = e >> 6, d = e & 63;
        tv[r][d] = V[r * Dc + d] * dsm[r];
    }
    __syncthreads();
    #pragma unroll
    for (int i = 0; i < 16; i++) {
        int e = tid + i * 256;
        int d = e >> 6, c = e & 63;
        float v = tv[c][d];
        __nv_bfloat16 h, l; split_bf(v, h, l);
        size_t o = ((size_t)bh * Dc + d) * Lc + m0 + c;
        g_vthi[o] = h; g_vtlo[o] = l;
    }
}

// ---------------- GEMM 3: out = E * Vs^T (128x64, BK=64) ----------------
__global__ void __launch_bounds__(256) k_pv_t(float* __restrict__ outF) {
    extern __shared__ char smem[];
    uint32_t sb = smem_u32(smem);
    const int tid = threadIdx.x;
    const int bh = blockIdx.y, b = bh >> 4, h = bh & 15;
    const int l0 = blockIdx.x * 128;

    float acc[32] = {};
    gemm_core<128, 64, 2, 32, 64>(g_ehi + ((size_t)bh * Lc + l0) * Lc,
                                  g_elo + ((size_t)bh * Lc + l0) * Lc, Lc,
                                  g_vthi + (size_t)bh * Dc * Lc,
                                  g_vtlo + (size_t)bh * Dc * Lc,       Lc,
                                  Lc, sb, acc);

    float* stage = reinterpret_cast<float*>(smem);     // 128 x pitch68
    const int wid = tid >> 5, lane = tid & 31;
    const int wm = wid >> 1, wn = wid & 1;
    #pragma unroll
    for (int mt = 0; mt < 2; mt++)
        #pragma unroll
        for (int nt = 0; nt < 4; nt++) {
            int r0 = wm * 32 + mt * 16 + (lane >> 2);
            int c0 = wn * 32 + nt * 8 + (lane & 3) * 2;
            float* d = acc + (mt * 4 + nt) * 4;
            stage[r0 * 68 + c0] = d[0]; stage[r0 * 68 + c0 + 1] = d[1];
            stage[(r0 + 8) * 68 + c0] = d[2]; stage[(r0 + 8) * 68 + c0 + 1] = d[3];
        }
    __syncthreads();
    for (int c = tid; c < 2048; c += 256) {
        int row = c >> 4, seg = c & 15;
        float4 v = *reinterpret_cast<float4*>(&stage[row * 68 + seg * 4]);
        __stcs(reinterpret_cast<float4*>(outF + ((size_t)b * Lc + l0 + row) * Ec + h * Dc + seg * 4), v);
    }
}

// ---------------- launch (fork-join overlap: projV || scores) ----------------
extern "C" void kernel_launch(void* const* d_in, const int* in_sizes, int n_in,
                              void* d_out, int out_size) {
    const float* x  = (const float*)d_in[0];
    const float* Wq = (const float*)d_in[1];
    const float* bq = (const float*)d_in[2];
    const float* Wk = (const float*)d_in[3];
    const float* bk = (const float*)d_in[4];
    const float* Wv = (const float*)d_in[5];
    const float* bv = (const float*)d_in[6];
    float* out = (float*)d_out;

    static bool init_done = false;
    static cudaStream_t s1;
    static cudaEvent_t ev0, evX, evW, evV;
    if (!init_done) {
        cudaStreamCreateWithFlags(&s1, cudaStreamNonBlocking);
        cudaEventCreateWithFlags(&ev0, cudaEventDisableTiming);
        cudaEventCreateWithFlags(&evX, cudaEventDisableTiming);
        cudaEventCreateWithFlags(&evW, cudaEventDisableTiming);
        cudaEventCreateWithFlags(&evV, cudaEventDisableTiming);
        cudaFuncSetAttribute(k_proj_t,   cudaFuncAttributeMaxDynamicSharedMemorySize, 110592);
        cudaFuncSetAttribute(k_scores_t, cudaFuncAttributeMaxDynamicSharedMemorySize, 81920);
        cudaFuncSetAttribute(k_pv_t,     cudaFuncAttributeMaxDynamicSharedMemorySize, 110592);
        init_done = true;
    }

    cudaEventRecord(ev0, 0);
    cudaStreamWaitEvent(s1, ev0, 0);
    conv_x<<<Mr * Ec / 1024, 256, 0, s1>>>(x);
    cudaEventRecord(evX, s1);

    conv_w<<<dim3(32, 32, 3), dim3(32, 8)>>>(Wq, Wk, Wv);
    cudaEventRecord(evW, 0);

    cudaStreamWaitEvent(0, evX, 0);
    k_proj_t<<<dim3(16, 32, 2), 256, 110592>>>(bq, bk, bv, 0);

    cudaStreamWaitEvent(s1, evW, 0);
    k_proj_t<<<dim3(16, 32, 1), 256, 110592, s1>>>(bq, bk, bv, 2);
    cudaEventRecord(evV, s1);

    k_scores_t<<<dim3(16, 16, 32), 256, 81920>>>();

    cudaStreamWaitEvent(0, evV, 0);
    k_vscale<<<dim3(32, 32), 256>>>();
    k_pv_t<<<dim3(16, 32), 256, 110592>>>(out);
}